// round 1
// baseline (speedup 1.0000x reference)
#include <cuda_runtime.h>
#include <cuda_bf16.h>
#include <math.h>

#define T_TOK 4096
#define DIM   2048
#define INTER 1024
#define NEXP  8
#define NE    9   // 8 routed + 1 shared pseudo-expert

// ---------------- scratch (device globals; no allocation allowed) ----------------
__device__ float g_hidden[9UL * 4096UL * 1024UL];   // [NE*T, INTER] post-SwiGLU hidden
__device__ int   g_pair_tok[NE * T_TOK];            // expert-major token lists
__device__ float g_pair_w[NE * T_TOK];              // routing weight per pair
__device__ int   g_cnt[NE];

// ---------------- kernel 0: reset counters ----------------
__global__ void init_kernel() {
    int i = threadIdx.x;
    if (i < NE) g_cnt[i] = (i == NEXP) ? T_TOK : 0;
}

// ---------------- kernel 1: gate (softmax + top2 + list build) + zero out ----------------
__global__ void gate_kernel(const float* __restrict__ x,
                            const float* __restrict__ gw,
                            float* __restrict__ out) {
    int t = blockIdx.x;
    const float* xr = x + (size_t)t * DIM;

    // zero this token's output row (out is poisoned by harness)
    float* orow = out + (size_t)t * DIM;
    for (int d = threadIdx.x; d < DIM; d += 256) orow[d] = 0.f;

    float acc[NEXP];
#pragma unroll
    for (int e = 0; e < NEXP; e++) acc[e] = 0.f;
    for (int d = threadIdx.x; d < DIM; d += 256) {
        float xv = xr[d];
#pragma unroll
        for (int e = 0; e < NEXP; e++) acc[e] += xv * gw[e * DIM + d];
    }
#pragma unroll
    for (int off = 16; off > 0; off >>= 1) {
#pragma unroll
        for (int e = 0; e < NEXP; e++)
            acc[e] += __shfl_down_sync(0xffffffffu, acc[e], off);
    }
    __shared__ float sw[8][NEXP];
    int warp = threadIdx.x >> 5, lane = threadIdx.x & 31;
    if (lane == 0) {
#pragma unroll
        for (int e = 0; e < NEXP; e++) sw[warp][e] = acc[e];
    }
    __syncthreads();
    if (threadIdx.x == 0) {
        float lg[NEXP];
#pragma unroll
        for (int e = 0; e < NEXP; e++) {
            float s = 0.f;
#pragma unroll
            for (int w = 0; w < 8; w++) s += sw[w][e];
            lg[e] = s;
        }
        float mx = lg[0];
#pragma unroll
        for (int e = 1; e < NEXP; e++) mx = fmaxf(mx, lg[e]);
        float p[NEXP]; float sum = 0.f;
#pragma unroll
        for (int e = 0; e < NEXP; e++) { p[e] = expf(lg[e] - mx); sum += p[e]; }
        float inv = 1.f / sum;
#pragma unroll
        for (int e = 0; e < NEXP; e++) p[e] *= inv;
        // top-2 (lower index wins ties, matching lax.top_k)
        int i1 = 0;
#pragma unroll
        for (int e = 1; e < NEXP; e++) if (p[e] > p[i1]) i1 = e;
        int i2 = (i1 == 0) ? 1 : 0;
#pragma unroll
        for (int e = 0; e < NEXP; e++) if (e != i1 && p[e] > p[i2]) i2 = e;

        int s1 = atomicAdd(&g_cnt[i1], 1);
        g_pair_tok[i1 * T_TOK + s1] = t;
        g_pair_w[i1 * T_TOK + s1] = p[i1];
        int s2 = atomicAdd(&g_cnt[i2], 1);
        g_pair_tok[i2 * T_TOK + s2] = t;
        g_pair_w[i2 * T_TOK + s2] = p[i2];
        // shared pseudo-expert: identity mapping, weight 1
        g_pair_tok[NEXP * T_TOK + t] = t;
        g_pair_w[NEXP * T_TOK + t] = 1.0f;
    }
}

// ---------------- GEMM tiling ----------------
#define BM 64
#define BN 64
#define BK 16
#define SPAD 4   // smem row pad (stride 68 floats, keeps float4 alignment)

// kernel 2: fused up-proj  H = silu(X W1^T) * (X W3^T)   (NT gemm, A gathered rows)
__global__ __launch_bounds__(256, 2)
void up_kernel(const float* __restrict__ x,
               const float* __restrict__ w1, const float* __restrict__ w3,
               const float* __restrict__ ws1, const float* __restrict__ ws3) {
    int e = blockIdx.z;
    int cnt = g_cnt[e];
    int m0 = blockIdx.y * BM;
    if (m0 >= cnt) return;
    int n0 = blockIdx.x * BN;

    const float* B1 = (e < NEXP) ? w1 + (size_t)e * INTER * DIM : ws1;
    const float* B3 = (e < NEXP) ? w3 + (size_t)e * INTER * DIM : ws3;

    __shared__ float As [BK][BM + SPAD];
    __shared__ float Bs1[BK][BN + SPAD];
    __shared__ float Bs3[BK][BN + SPAD];

    int tid = threadIdx.x;
    int lr = tid >> 2;            // 0..63: tile row this thread loads
    int lk = (tid & 3) * 4;       // 0,4,8,12: k offset (float4)

    int arow = m0 + lr;
    int atok = (arow < cnt) ? g_pair_tok[e * T_TOK + arow] : -1;
    const float* Arow  = x  + (atok >= 0 ? (size_t)atok * DIM : 0);
    const float* B1row = B1 + (size_t)(n0 + lr) * DIM;
    const float* B3row = B3 + (size_t)(n0 + lr) * DIM;

    int tm = (tid & 15) * 4;      // micro-tile M offset
    int tn = (tid >> 4) * 4;      // micro-tile N offset

    float acc1[4][4], acc3[4][4];
#pragma unroll
    for (int i = 0; i < 4; i++)
#pragma unroll
        for (int j = 0; j < 4; j++) { acc1[i][j] = 0.f; acc3[i][j] = 0.f; }

    for (int k0 = 0; k0 < DIM; k0 += BK) {
        float4 a  = (atok >= 0) ? *(const float4*)(Arow  + k0 + lk) : make_float4(0,0,0,0);
        float4 b1 = *(const float4*)(B1row + k0 + lk);
        float4 b3 = *(const float4*)(B3row + k0 + lk);
        __syncthreads();
        As [lk+0][lr]=a.x;  As [lk+1][lr]=a.y;  As [lk+2][lr]=a.z;  As [lk+3][lr]=a.w;
        Bs1[lk+0][lr]=b1.x; Bs1[lk+1][lr]=b1.y; Bs1[lk+2][lr]=b1.z; Bs1[lk+3][lr]=b1.w;
        Bs3[lk+0][lr]=b3.x; Bs3[lk+1][lr]=b3.y; Bs3[lk+2][lr]=b3.z; Bs3[lk+3][lr]=b3.w;
        __syncthreads();
#pragma unroll
        for (int kk = 0; kk < BK; kk++) {
            float4 av  = *(const float4*)&As [kk][tm];
            float4 b1v = *(const float4*)&Bs1[kk][tn];
            float4 b3v = *(const float4*)&Bs3[kk][tn];
            float am[4] = {av.x, av.y, av.z, av.w};
            float v1[4] = {b1v.x, b1v.y, b1v.z, b1v.w};
            float v3[4] = {b3v.x, b3v.y, b3v.z, b3v.w};
#pragma unroll
            for (int i = 0; i < 4; i++)
#pragma unroll
                for (int j = 0; j < 4; j++) {
                    acc1[i][j] += am[i] * v1[j];
                    acc3[i][j] += am[i] * v3[j];
                }
        }
    }
#pragma unroll
    for (int i = 0; i < 4; i++) {
        int row = m0 + tm + i;
        if (row < cnt) {
            size_t base = ((size_t)e * T_TOK + row) * INTER + n0 + tn;
#pragma unroll
            for (int j = 0; j < 4; j++) {
                float h1 = acc1[i][j], h3 = acc3[i][j];
                float s = h1 / (1.f + __expf(-h1));   // silu
                g_hidden[base + j] = s * h3;
            }
        }
    }
}

// kernel 3: down-proj + weighted scatter-add combine
__global__ __launch_bounds__(256, 2)
void down_kernel(const float* __restrict__ w2, const float* __restrict__ ws2,
                 float* __restrict__ out) {
    int e = blockIdx.z;
    int cnt = g_cnt[e];
    int m0 = blockIdx.y * BM;
    if (m0 >= cnt) return;
    int n0 = blockIdx.x * BN;

    const float* B = (e < NEXP) ? w2 + (size_t)e * DIM * INTER : ws2;

    __shared__ float As[BK][BM + SPAD];
    __shared__ float Bs[BK][BN + SPAD];

    int tid = threadIdx.x;
    int lr = tid >> 2;
    int lk = (tid & 3) * 4;

    int arow = m0 + lr;
    bool avalid = (arow < cnt);
    const float* Arow = &g_hidden[((size_t)e * T_TOK + (avalid ? arow : 0)) * INTER];
    const float* Brow = B + (size_t)(n0 + lr) * INTER;

    int tm = (tid & 15) * 4;
    int tn = (tid >> 4) * 4;

    float acc[4][4];
#pragma unroll
    for (int i = 0; i < 4; i++)
#pragma unroll
        for (int j = 0; j < 4; j++) acc[i][j] = 0.f;

    for (int k0 = 0; k0 < INTER; k0 += BK) {
        float4 a = avalid ? *(const float4*)(Arow + k0 + lk) : make_float4(0,0,0,0);
        float4 b = *(const float4*)(Brow + k0 + lk);
        __syncthreads();
        As[lk+0][lr]=a.x; As[lk+1][lr]=a.y; As[lk+2][lr]=a.z; As[lk+3][lr]=a.w;
        Bs[lk+0][lr]=b.x; Bs[lk+1][lr]=b.y; Bs[lk+2][lr]=b.z; Bs[lk+3][lr]=b.w;
        __syncthreads();
#pragma unroll
        for (int kk = 0; kk < BK; kk++) {
            float4 av = *(const float4*)&As[kk][tm];
            float4 bv = *(const float4*)&Bs[kk][tn];
            float am[4] = {av.x, av.y, av.z, av.w};
            float bm[4] = {bv.x, bv.y, bv.z, bv.w};
#pragma unroll
            for (int i = 0; i < 4; i++)
#pragma unroll
                for (int j = 0; j < 4; j++)
                    acc[i][j] += am[i] * bm[j];
        }
    }
#pragma unroll
    for (int i = 0; i < 4; i++) {
        int row = m0 + tm + i;
        if (row < cnt) {
            int tok  = g_pair_tok[e * T_TOK + row];
            float wv = g_pair_w[e * T_TOK + row];
            float* orow = out + (size_t)tok * DIM + n0 + tn;
#pragma unroll
            for (int j = 0; j < 4; j++)
                atomicAdd(&orow[j], acc[i][j] * wv);
        }
    }
}

// ---------------- launch ----------------
extern "C" void kernel_launch(void* const* d_in, const int* in_sizes, int n_in,
                              void* d_out, int out_size) {
    const float* x      = (const float*)d_in[0];
    const float* gate_w = (const float*)d_in[1];
    const float* w1     = (const float*)d_in[2];
    const float* w2     = (const float*)d_in[3];
    const float* w3     = (const float*)d_in[4];
    const float* ws1    = (const float*)d_in[5];
    const float* ws2    = (const float*)d_in[6];
    const float* ws3    = (const float*)d_in[7];
    float* out = (float*)d_out;

    init_kernel<<<1, 32>>>();
    gate_kernel<<<T_TOK, 256>>>(x, gate_w, out);
    {
        dim3 grid(INTER / BN, T_TOK / BM, NE);
        up_kernel<<<grid, 256>>>(x, w1, w3, ws1, ws3);
    }
    {
        dim3 grid(DIM / BN, T_TOK / BM, NE);
        down_kernel<<<grid, 256>>>(w2, ws2, out);
    }
}

// round 2
// speedup vs baseline: 3.1210x; 3.1210x over previous
#include <cuda_runtime.h>
#include <stdint.h>
#include <math.h>

#define T_TOK 4096
#define DIM   2048
#define INTER 1024
#define NEXP  8
#define NE    9      // 8 routed + 1 shared pseudo-expert
#define BK    16
#define SA    20     // smem row stride (floats): 16 + 4 pad

// ---------------- scratch (device globals; no allocation allowed) ----------------
__device__ float g_hidden [(size_t)NE * T_TOK * INTER];  // [e*T+slot][INTER] post-SwiGLU
__device__ float g_pairout[(size_t)NE * T_TOK * DIM];    // [e*T+slot][DIM] weighted expert out
__device__ int   g_pair_tok[NE * T_TOK];
__device__ float g_pair_w [NE * T_TOK];
__device__ int   g_tok_rows[T_TOK * 2];                  // token -> its 2 routed pair rows
__device__ int   g_cnt[NE];

// ---------------- PTX helpers ----------------
__device__ __forceinline__ uint32_t smem_u32(const void* p) {
    return (uint32_t)__cvta_generic_to_shared(p);
}
__device__ __forceinline__ void cp16(uint32_t dst, const float* src, bool valid) {
    int sz = valid ? 16 : 0;
    asm volatile("cp.async.cg.shared.global [%0], [%1], 16, %2;\n"
                 :: "r"(dst), "l"(src), "r"(sz));
}
#define CP_COMMIT() asm volatile("cp.async.commit_group;\n")
#define CP_WAIT1()  asm volatile("cp.async.wait_group 1;\n")
#define CP_WAIT0()  asm volatile("cp.async.wait_group 0;\n")

__device__ __forceinline__ uint32_t f2tf(float f) {
    uint32_t u; asm("cvt.rna.tf32.f32 %0, %1;" : "=r"(u) : "f"(f)); return u;
}
__device__ __forceinline__ void mma_tf32(float* c, const uint32_t* a, const uint32_t* b) {
    asm volatile("mma.sync.aligned.m16n8k8.row.col.f32.tf32.tf32.f32 "
        "{%0,%1,%2,%3}, {%4,%5,%6,%7}, {%8,%9}, {%0,%1,%2,%3};\n"
        : "+f"(c[0]), "+f"(c[1]), "+f"(c[2]), "+f"(c[3])
        : "r"(a[0]), "r"(a[1]), "r"(a[2]), "r"(a[3]), "r"(b[0]), "r"(b[1]));
}

// ---------------- kernel 0: reset counters ----------------
__global__ void init_kernel() {
    int i = threadIdx.x;
    if (i < NE) g_cnt[i] = (i == NEXP) ? T_TOK : 0;
}

// ---------------- kernel 1: gate (softmax + top2 + list build) ----------------
__global__ void gate_kernel(const float* __restrict__ x,
                            const float* __restrict__ gw) {
    int t = blockIdx.x;
    const float* xr = x + (size_t)t * DIM;

    float acc[NEXP];
#pragma unroll
    for (int e = 0; e < NEXP; e++) acc[e] = 0.f;
    for (int d = threadIdx.x; d < DIM; d += 256) {
        float xv = xr[d];
#pragma unroll
        for (int e = 0; e < NEXP; e++) acc[e] += xv * gw[e * DIM + d];
    }
#pragma unroll
    for (int off = 16; off > 0; off >>= 1) {
#pragma unroll
        for (int e = 0; e < NEXP; e++)
            acc[e] += __shfl_down_sync(0xffffffffu, acc[e], off);
    }
    __shared__ float sw[8][NEXP];
    int warp = threadIdx.x >> 5, lane = threadIdx.x & 31;
    if (lane == 0) {
#pragma unroll
        for (int e = 0; e < NEXP; e++) sw[warp][e] = acc[e];
    }
    __syncthreads();
    if (threadIdx.x == 0) {
        float lg[NEXP];
#pragma unroll
        for (int e = 0; e < NEXP; e++) {
            float s = 0.f;
#pragma unroll
            for (int w = 0; w < 8; w++) s += sw[w][e];
            lg[e] = s;
        }
        float mx = lg[0];
#pragma unroll
        for (int e = 1; e < NEXP; e++) mx = fmaxf(mx, lg[e]);
        float p[NEXP]; float sum = 0.f;
#pragma unroll
        for (int e = 0; e < NEXP; e++) { p[e] = expf(lg[e] - mx); sum += p[e]; }
        float inv = 1.f / sum;
#pragma unroll
        for (int e = 0; e < NEXP; e++) p[e] *= inv;
        int i1 = 0;
#pragma unroll
        for (int e = 1; e < NEXP; e++) if (p[e] > p[i1]) i1 = e;
        int i2 = (i1 == 0) ? 1 : 0;
#pragma unroll
        for (int e = 0; e < NEXP; e++) if (e != i1 && p[e] > p[i2]) i2 = e;

        int s1 = atomicAdd(&g_cnt[i1], 1);
        g_pair_tok[i1 * T_TOK + s1] = t;
        g_pair_w [i1 * T_TOK + s1] = p[i1];
        int s2 = atomicAdd(&g_cnt[i2], 1);
        g_pair_tok[i2 * T_TOK + s2] = t;
        g_pair_w [i2 * T_TOK + s2] = p[i2];
        g_tok_rows[2 * t]     = i1 * T_TOK + s1;
        g_tok_rows[2 * t + 1] = i2 * T_TOK + s2;
        // shared pseudo-expert: identity mapping, weight 1
        g_pair_tok[NEXP * T_TOK + t] = t;
        g_pair_w [NEXP * T_TOK + t] = 1.0f;
    }
}

// ---------------- kernel 2: fused up-proj, TF32 mma, H = silu(XW1^T)*(XW3^T) ----
#define UP_BM 128
#define UP_BN 64

__global__ __launch_bounds__(256, 2)
void up_kernel(const float* __restrict__ x,
               const float* __restrict__ w1, const float* __restrict__ w3,
               const float* __restrict__ ws1, const float* __restrict__ ws3) {
    __shared__ float As [2][UP_BM * SA];
    __shared__ float B1s[2][UP_BN * SA];
    __shared__ float B3s[2][UP_BN * SA];

    int e = blockIdx.z;
    int cnt = g_cnt[e];
    int m0 = blockIdx.y * UP_BM;
    if (m0 >= cnt) return;
    int n0 = blockIdx.x * UP_BN;

    const float* B1 = (e < NEXP) ? w1 + (size_t)e * INTER * DIM : ws1;
    const float* B3 = (e < NEXP) ? w3 + (size_t)e * INTER * DIM : ws3;

    int tid = threadIdx.x;
    // A: 2 float4 chunks per thread (rows 0..63, 64..127)
    int ar0 = tid >> 2, ar1 = ar0 + 64;
    int ak  = (tid & 3) * 4;
    bool v0 = (m0 + ar0 < cnt), v1 = (m0 + ar1 < cnt);
    int t0 = v0 ? g_pair_tok[e * T_TOK + m0 + ar0] : 0;
    int t1 = v1 ? g_pair_tok[e * T_TOK + m0 + ar1] : 0;
    const float* asrc0 = x + (size_t)t0 * DIM + ak;
    const float* asrc1 = x + (size_t)t1 * DIM + ak;
    // B: 1 chunk per thread
    int br = tid >> 2, bk = (tid & 3) * 4;
    const float* b1src = B1 + (size_t)(n0 + br) * DIM + bk;
    const float* b3src = B3 + (size_t)(n0 + br) * DIM + bk;

    uint32_t dA0[2], dA1[2], dB1[2], dB3[2];
#pragma unroll
    for (int b = 0; b < 2; b++) {
        dA0[b] = smem_u32(&As [b][ar0 * SA + ak]);
        dA1[b] = smem_u32(&As [b][ar1 * SA + ak]);
        dB1[b] = smem_u32(&B1s[b][br  * SA + bk]);
        dB3[b] = smem_u32(&B3s[b][br  * SA + bk]);
    }

    int w = tid >> 5, lane = tid & 31;
    int g = lane >> 2, tg = lane & 3;
    int mw = (w & 3) * 32, nw = (w >> 2) * 32;

    float acc1[2][4][4], acc3[2][4][4];
#pragma unroll
    for (int mi = 0; mi < 2; mi++)
#pragma unroll
        for (int ni = 0; ni < 4; ni++)
#pragma unroll
            for (int q = 0; q < 4; q++) { acc1[mi][ni][q] = 0.f; acc3[mi][ni][q] = 0.f; }

    // prologue: stage 0
    cp16(dA0[0], asrc0, v0); cp16(dA1[0], asrc1, v1);
    cp16(dB1[0], b1src, true); cp16(dB3[0], b3src, true);
    CP_COMMIT();

    int buf = 0;
    for (int k0 = 0; k0 < DIM; k0 += BK) {
        if (k0 + BK < DIM) {
            int nb = buf ^ 1, kn = k0 + BK;
            cp16(dA0[nb], asrc0 + kn, v0); cp16(dA1[nb], asrc1 + kn, v1);
            cp16(dB1[nb], b1src + kn, true); cp16(dB3[nb], b3src + kn, true);
            CP_COMMIT();
            CP_WAIT1();
        } else {
            CP_WAIT0();
        }
        __syncthreads();
#pragma unroll
        for (int ks = 0; ks < 2; ks++) {
            int kb = ks * 8;
            uint32_t afr[2][4];
#pragma unroll
            for (int mi = 0; mi < 2; mi++) {
                const float* ab = &As[buf][(mw + mi * 16 + g) * SA + kb + tg];
                afr[mi][0] = f2tf(ab[0]);
                afr[mi][1] = f2tf(ab[8 * SA]);
                afr[mi][2] = f2tf(ab[4]);
                afr[mi][3] = f2tf(ab[8 * SA + 4]);
            }
#pragma unroll
            for (int ni = 0; ni < 4; ni++) {
                const float* b1b = &B1s[buf][(nw + ni * 8 + g) * SA + kb + tg];
                const float* b3b = &B3s[buf][(nw + ni * 8 + g) * SA + kb + tg];
                uint32_t b1f[2] = { f2tf(b1b[0]), f2tf(b1b[4]) };
                uint32_t b3f[2] = { f2tf(b3b[0]), f2tf(b3b[4]) };
#pragma unroll
                for (int mi = 0; mi < 2; mi++) {
                    mma_tf32(acc1[mi][ni], afr[mi], b1f);
                    mma_tf32(acc3[mi][ni], afr[mi], b3f);
                }
            }
        }
        __syncthreads();
        buf ^= 1;
    }

    // epilogue: silu(h1)*h3 -> g_hidden
#pragma unroll
    for (int mi = 0; mi < 2; mi++)
#pragma unroll
        for (int h = 0; h < 2; h++) {
            int slot = m0 + mw + mi * 16 + g + h * 8;
            if (slot < cnt) {
                size_t base = ((size_t)e * T_TOK + slot) * INTER + n0 + nw;
#pragma unroll
                for (int ni = 0; ni < 4; ni++) {
                    float h1a = acc1[mi][ni][h * 2], h1b = acc1[mi][ni][h * 2 + 1];
                    float h3a = acc3[mi][ni][h * 2], h3b = acc3[mi][ni][h * 2 + 1];
                    float2 st;
                    st.x = (h1a / (1.f + __expf(-h1a))) * h3a;
                    st.y = (h1b / (1.f + __expf(-h1b))) * h3b;
                    *(float2*)&g_hidden[base + ni * 8 + tg * 2] = st;
                }
            }
        }
}

// ---------------- kernel 3: down-proj, TF32 mma, weighted store (no atomics) ----
#define DN_BM 128
#define DN_BN 128

__global__ __launch_bounds__(256, 2)
void down_kernel(const float* __restrict__ w2, const float* __restrict__ ws2) {
    __shared__ float As[2][DN_BM * SA];
    __shared__ float Bs[2][DN_BN * SA];

    int e = blockIdx.z;
    int cnt = g_cnt[e];
    int m0 = blockIdx.y * DN_BM;
    if (m0 >= cnt) return;
    int n0 = blockIdx.x * DN_BN;

    const float* B = (e < NEXP) ? w2 + (size_t)e * DIM * INTER : ws2;

    int tid = threadIdx.x;
    int ar0 = tid >> 2, ar1 = ar0 + 64;
    int ak  = (tid & 3) * 4;
    bool v0 = (m0 + ar0 < cnt), v1 = (m0 + ar1 < cnt);
    const float* asrc0 = g_hidden + ((size_t)e * T_TOK + (v0 ? m0 + ar0 : 0)) * INTER + ak;
    const float* asrc1 = g_hidden + ((size_t)e * T_TOK + (v1 ? m0 + ar1 : 0)) * INTER + ak;
    const float* bsrc0 = B + (size_t)(n0 + ar0) * INTER + ak;
    const float* bsrc1 = B + (size_t)(n0 + ar1) * INTER + ak;

    uint32_t dA0[2], dA1[2], dB0[2], dB1[2];
#pragma unroll
    for (int b = 0; b < 2; b++) {
        dA0[b] = smem_u32(&As[b][ar0 * SA + ak]);
        dA1[b] = smem_u32(&As[b][ar1 * SA + ak]);
        dB0[b] = smem_u32(&Bs[b][ar0 * SA + ak]);
        dB1[b] = smem_u32(&Bs[b][ar1 * SA + ak]);
    }

    int w = tid >> 5, lane = tid & 31;
    int g = lane >> 2, tg = lane & 3;
    int mw = (w & 3) * 32, nw = (w >> 2) * 64;

    float acc[2][8][4];
#pragma unroll
    for (int mi = 0; mi < 2; mi++)
#pragma unroll
        for (int ni = 0; ni < 8; ni++)
#pragma unroll
            for (int q = 0; q < 4; q++) acc[mi][ni][q] = 0.f;

    cp16(dA0[0], asrc0, v0); cp16(dA1[0], asrc1, v1);
    cp16(dB0[0], bsrc0, true); cp16(dB1[0], bsrc1, true);
    CP_COMMIT();

    int buf = 0;
    for (int k0 = 0; k0 < INTER; k0 += BK) {
        if (k0 + BK < INTER) {
            int nb = buf ^ 1, kn = k0 + BK;
            cp16(dA0[nb], asrc0 + kn, v0); cp16(dA1[nb], asrc1 + kn, v1);
            cp16(dB0[nb], bsrc0 + kn, true); cp16(dB1[nb], bsrc1 + kn, true);
            CP_COMMIT();
            CP_WAIT1();
        } else {
            CP_WAIT0();
        }
        __syncthreads();
#pragma unroll
        for (int ks = 0; ks < 2; ks++) {
            int kb = ks * 8;
            uint32_t afr[2][4];
#pragma unroll
            for (int mi = 0; mi < 2; mi++) {
                const float* ab = &As[buf][(mw + mi * 16 + g) * SA + kb + tg];
                afr[mi][0] = f2tf(ab[0]);
                afr[mi][1] = f2tf(ab[8 * SA]);
                afr[mi][2] = f2tf(ab[4]);
                afr[mi][3] = f2tf(ab[8 * SA + 4]);
            }
#pragma unroll
            for (int ni = 0; ni < 8; ni++) {
                const float* bb = &Bs[buf][(nw + ni * 8 + g) * SA + kb + tg];
                uint32_t bf[2] = { f2tf(bb[0]), f2tf(bb[4]) };
#pragma unroll
                for (int mi = 0; mi < 2; mi++)
                    mma_tf32(acc[mi][ni], afr[mi], bf);
            }
        }
        __syncthreads();
        buf ^= 1;
    }

    // epilogue: weight-fold + plain store to pairout
#pragma unroll
    for (int mi = 0; mi < 2; mi++)
#pragma unroll
        for (int h = 0; h < 2; h++) {
            int slot = m0 + mw + mi * 16 + g + h * 8;
            if (slot < cnt) {
                float wv = g_pair_w[e * T_TOK + slot];
                size_t base = ((size_t)e * T_TOK + slot) * DIM + n0 + nw;
#pragma unroll
                for (int ni = 0; ni < 8; ni++) {
                    float2 st;
                    st.x = acc[mi][ni][h * 2]     * wv;
                    st.y = acc[mi][ni][h * 2 + 1] * wv;
                    *(float2*)&g_pairout[base + ni * 8 + tg * 2] = st;
                }
            }
        }
}

// ---------------- kernel 4: combine (2 routed rows + shared row) ----------------
__global__ void combine_kernel(float* __restrict__ out) {
    int t = blockIdx.x;
    int r1 = g_tok_rows[2 * t], r2 = g_tok_rows[2 * t + 1];
    const float4* p1 = (const float4*)(g_pairout + (size_t)r1 * DIM);
    const float4* p2 = (const float4*)(g_pairout + (size_t)r2 * DIM);
    const float4* ps = (const float4*)(g_pairout + ((size_t)NEXP * T_TOK + t) * DIM);
    float4* o = (float4*)(out + (size_t)t * DIM);
#pragma unroll
    for (int i = threadIdx.x; i < DIM / 4; i += 256) {
        float4 a = p1[i], b = p2[i], c = ps[i];
        o[i] = make_float4(a.x + b.x + c.x, a.y + b.y + c.y,
                           a.z + b.z + c.z, a.w + b.w + c.w);
    }
}

// ---------------- launch ----------------
extern "C" void kernel_launch(void* const* d_in, const int* in_sizes, int n_in,
                              void* d_out, int out_size) {
    const float* x      = (const float*)d_in[0];
    const float* gate_w = (const float*)d_in[1];
    const float* w1     = (const float*)d_in[2];
    const float* w2     = (const float*)d_in[3];
    const float* w3     = (const float*)d_in[4];
    const float* ws1    = (const float*)d_in[5];
    const float* ws2    = (const float*)d_in[6];
    const float* ws3    = (const float*)d_in[7];
    float* out = (float*)d_out;

    init_kernel<<<1, 32>>>();
    gate_kernel<<<T_TOK, 256>>>(x, gate_w);
    {
        dim3 grid(INTER / UP_BN, T_TOK / UP_BM, NE);
        up_kernel<<<grid, 256>>>(x, w1, w3, ws1, ws3);
    }
    {
        dim3 grid(DIM / DN_BN, T_TOK / DN_BM, NE);
        down_kernel<<<grid, 256>>>(w2, ws2);
    }
    combine_kernel<<<T_TOK, 256>>>(out);
}